// round 1
// baseline (speedup 1.0000x reference)
#include <cuda_runtime.h>

#define BB 2
#define SS 2048
#define EE 512
#define HH 8
#define DD 64
#define LB 128
#define NR 129

#define TI 128
#define TJ 64

// smem strides (floats)
#define SQ 132
#define SP 132
#define SK 68
#define SPT 132
#define SMEM_FLOATS 42752   // see layout below

__device__ float g_q[BB*HH*SS*DD];
__device__ float g_k[BB*HH*SS*DD];
__device__ float g_v[BB*HH*SS*DD];
__device__ float g_o[BB*HH*SS*DD];

// ---------------------------------------------------------------------------
// Projection: out[b,h,s,d] = sum_e xs[b,s,e] * w[h,e,d]   for w in {wq,wk,wv}
// grid: (S/64, B*H, 3), 256 threads. 64x64 tile, BK=32, 4x4 register tile.
// ---------------------------------------------------------------------------
__global__ __launch_bounds__(256) void proj_kernel(
    const float* __restrict__ xs,
    const float* __restrict__ wq,
    const float* __restrict__ wk,
    const float* __restrict__ wv) {
  __shared__ float xst[32][68];   // [e][s] transposed (pad 68 -> 4-way max conflicts)
  __shared__ float wt[32][64];    // [e][d]
  int bh = blockIdx.y;
  int b = bh / HH, h = bh % HH;
  int s0 = blockIdx.x * 64;
  const float* w  = (blockIdx.z == 0) ? wq : ((blockIdx.z == 1) ? wk : wv);
  float* out      = (blockIdx.z == 0) ? g_q : ((blockIdx.z == 1) ? g_k : g_v);
  int tid = threadIdx.x;
  int ti = tid >> 4, tj = tid & 15;
  float acc[4][4] = {};
  const float* xsb = xs + (size_t)b * SS * EE + (size_t)s0 * EE;
  const float* wb  = w + (size_t)h * EE * DD;
  for (int e0 = 0; e0 < EE; e0 += 32) {
    for (int t = tid; t < 64*32; t += 256) {
      int e = t & 31, srow = t >> 5;
      xst[e][srow] = xsb[srow * EE + e0 + e];
    }
    for (int t = tid; t < 32*16; t += 256) {
      int d4 = t & 15, e = t >> 4;
      *(float4*)&wt[e][d4*4] = *(const float4*)&wb[(e0+e)*DD + d4*4];
    }
    __syncthreads();
    #pragma unroll 8
    for (int e = 0; e < 32; e++) {
      float xf[4], wf[4];
      *(float4*)xf = *(const float4*)&xst[e][ti*4];
      *(float4*)wf = *(const float4*)&wt[e][tj*4];
      #pragma unroll
      for (int i = 0; i < 4; i++)
        #pragma unroll
        for (int j = 0; j < 4; j++)
          acc[i][j] = fmaf(xf[i], wf[j], acc[i][j]);
    }
    __syncthreads();
  }
  float* ob = out + ((size_t)bh * SS + s0) * DD;
  #pragma unroll
  for (int i = 0; i < 4; i++) {
    float4 o4 = make_float4(acc[i][0], acc[i][1], acc[i][2], acc[i][3]);
    *(float4*)&ob[(ti*4 + i) * DD + tj*4] = o4;
  }
}

// ---------------------------------------------------------------------------
// Attention.
// One block per (b*h, 128-query tile). 256 threads.
// smem layout (floats):
//   qst  @ 0      : [64 d][132]  q transposed, pre-scaled by 1/8      (8448)
//   p    @ 8448   : [128 i][132] rel logits p[i][r]=q_i.a_k[r]/8      (16896)
//   kst  @ 25344  : [64 d][68]   k tile transposed                    (4352)
//   vs   @ 29696  : [64 j][64 v] v tile                               (4096)
//   Pt   @ 33792  : [64 j][132 i] window probs (unnormalized)         (8448)
//   akt  @ 25344  : [64 d][132]  a_k transposed (phase A only, overlaps kst+vs)
//   sums @ 42240  : sumB/sumW/sumA/den, 128 each                      (512)
// total 42752 floats = 171008 B
// ---------------------------------------------------------------------------
__global__ __launch_bounds__(256) void attn_kernel(const float* __restrict__ a_k) {
  extern __shared__ float sm[];
  float* qst  = sm;
  float* p    = sm + 8448;
  float* kst  = sm + 25344;
  float* vs   = sm + 29696;
  float* Pt   = sm + 33792;
  float* akt  = sm + 25344;
  float* sumB = sm + 42240;
  float* sumW = sumB + 128;
  float* sumA = sumW + 128;
  float* den  = sumA + 128;

  int tid = threadIdx.x;
  int bh = blockIdx.y;
  int I0 = blockIdx.x * TI;
  const float* qg = g_q + (size_t)bh * SS * DD;
  const float* kg = g_k + (size_t)bh * SS * DD;
  const float* vg = g_v + (size_t)bh * SS * DD;

  // load q tile transposed, pre-scaled by 1/sqrt(VDIM)=1/8
  for (int t = tid; t < TI*DD; t += 256) {
    int d = t & 63, i = t >> 6;
    qst[d*SQ + i] = qg[(size_t)(I0+i)*DD + d] * 0.125f;
  }
  // load a_k transposed
  for (int t = tid; t < NR*DD; t += 256) {
    int d = t & 63, r = t >> 6;
    akt[d*132 + r] = a_k[r*DD + d];
  }
  if (tid < 128) { sumB[tid] = 0.f; sumW[tid] = 0.f; sumA[tid] = 0.f; }
  __syncthreads();

  int ti = tid >> 4;   // 16 groups x 8 i-rows
  int tj = tid & 15;   // 16 groups (j / r / v dims)

  // ---- Phase A: p[i][r] = q_i . a_k[r] / 8,  r = 0..128 ----
  {
    float acc[8][8] = {};
    #pragma unroll 2
    for (int d = 0; d < 64; d++) {
      float qf[8], af[8];
      *(float4*)&qf[0] = *(const float4*)&qst[d*SQ + ti*8];
      *(float4*)&qf[4] = *(const float4*)&qst[d*SQ + ti*8 + 4];
      *(float4*)&af[0] = *(const float4*)&akt[d*132 + tj*8];
      *(float4*)&af[4] = *(const float4*)&akt[d*132 + tj*8 + 4];
      #pragma unroll
      for (int i = 0; i < 8; i++)
        #pragma unroll
        for (int r = 0; r < 8; r++)
          acc[i][r] = fmaf(qf[i], af[r], acc[i][r]);
    }
    #pragma unroll
    for (int i = 0; i < 8; i++) {
      *(float4*)&p[(ti*8+i)*SP + tj*8]     = make_float4(acc[i][0],acc[i][1],acc[i][2],acc[i][3]);
      *(float4*)&p[(ti*8+i)*SP + tj*8 + 4] = make_float4(acc[i][4],acc[i][5],acc[i][6],acc[i][7]);
    }
    if (tid < 128) {  // r = 128 column
      float s = 0.f;
      for (int d = 0; d < 64; d++) s = fmaf(qst[d*SQ + tid], akt[d*132 + 128], s);
      p[tid*SP + 128] = s;
    }
  }
  __syncthreads();

  float Oacc[8][4] = {};   // numerator accumulators: 8 i x 4 v (v = tj*4+vv)

  for (int jt = 0; jt < SS/TJ; jt++) {
    int j0 = jt * TJ;
    // 0 = pure-below (all j <= i-129), 2 = pure-above (all j > i), 1 = mixed/window
    int cls = (j0 + TJ <= I0 - LB) ? 0 : ((j0 >= I0 + TI) ? 2 : 1);

    __syncthreads();
    for (int t = tid; t < TJ*DD; t += 256) {
      int d = t & 63, j = t >> 6;
      kst[d*SK + j] = kg[(size_t)(j0+j)*DD + d];
    }
    if (cls == 1) {
      for (int t = tid; t < TJ*16; t += 256) {
        int v4 = t & 15, j = t >> 4;
        *(float4*)&vs[j*64 + v4*4] = *(const float4*)&vg[(size_t)(j0+j)*DD + v4*4];
      }
    }
    __syncthreads();

    // scores: acc[i][j] = q_i . k_j / 8
    float acc[8][4] = {};
    #pragma unroll 4
    for (int d = 0; d < 64; d++) {
      float qf[8], kf[4];
      *(float4*)&qf[0] = *(const float4*)&qst[d*SQ + ti*8];
      *(float4*)&qf[4] = *(const float4*)&qst[d*SQ + ti*8 + 4];
      *(float4*)kf     = *(const float4*)&kst[d*SK + tj*4];
      #pragma unroll
      for (int i = 0; i < 8; i++)
        #pragma unroll
        for (int j = 0; j < 4; j++)
          acc[i][j] = fmaf(qf[i], kf[j], acc[i][j]);
    }

    if (cls != 1) {
      // pure tile: only row-sum of exp needed
      float* dst = (cls == 0) ? sumB : sumA;
      #pragma unroll
      for (int i = 0; i < 8; i++) {
        float rs = __expf(acc[i][0]) + __expf(acc[i][1]) + __expf(acc[i][2]) + __expf(acc[i][3]);
        rs += __shfl_xor_sync(0xffffffffu, rs, 8);
        rs += __shfl_xor_sync(0xffffffffu, rs, 4);
        rs += __shfl_xor_sync(0xffffffffu, rs, 2);
        rs += __shfl_xor_sync(0xffffffffu, rs, 1);
        if (tj == 0) dst[ti*8+i] += rs;
      }
    } else {
      // mixed tile: classify each element, build window-prob tile Pt
      #pragma unroll
      for (int i = 0; i < 8; i++) {
        int il = ti*8 + i;
        int ig = I0 + il;
        float rb = 0.f, rw = 0.f, ra = 0.f;
        #pragma unroll
        for (int j = 0; j < 4; j++) {
          int jg = j0 + tj*4 + j;
          int r = jg - ig + LB;
          float pw = 0.f;
          if (r >= 0 && r <= LB) {
            pw = __expf(acc[i][j] + p[il*SP + r]);
            rw += pw;
          } else if (r < 0) {
            rb += __expf(acc[i][j]);
          } else {
            ra += __expf(acc[i][j]);
          }
          Pt[(tj*4+j)*SPT + il] = pw;
        }
        #pragma unroll
        for (int m = 8; m >= 1; m >>= 1) {
          rb += __shfl_xor_sync(0xffffffffu, rb, m);
          rw += __shfl_xor_sync(0xffffffffu, rw, m);
          ra += __shfl_xor_sync(0xffffffffu, ra, m);
        }
        if (tj == 0) { sumB[il] += rb; sumW[il] += rw; sumA[il] += ra; }
      }
      __syncthreads();
      // PV: Oacc[i][v] += sum_j Pt[j][i] * vs[j][v]
      #pragma unroll 4
      for (int j = 0; j < TJ; j++) {
        float pf[8], vf[4];
        *(float4*)&pf[0] = *(const float4*)&Pt[j*SPT + ti*8];
        *(float4*)&pf[4] = *(const float4*)&Pt[j*SPT + ti*8 + 4];
        *(float4*)vf     = *(const float4*)&vs[j*64 + tj*4];
        #pragma unroll
        for (int i = 0; i < 8; i++)
          #pragma unroll
          for (int v = 0; v < 4; v++)
            Oacc[i][v] = fmaf(pf[i], vf[v], Oacc[i][v]);
      }
    }
  }
  __syncthreads();
  // denominator: exp(c0)*below + window + exp(c1)*above
  if (tid < 128) {
    float c0 = p[tid*SP];
    float c1 = p[tid*SP + 128];
    den[tid] = __expf(c0) * sumB[tid] + sumW[tid] + __expf(c1) * sumA[tid];
  }
  __syncthreads();
  float* og = g_o + (size_t)bh * SS * DD;
  #pragma unroll
  for (int i = 0; i < 8; i++) {
    float dinv = 1.0f / den[ti*8+i];
    float4 o4 = make_float4(Oacc[i][0]*dinv, Oacc[i][1]*dinv, Oacc[i][2]*dinv, Oacc[i][3]*dinv);
    *(float4*)&og[(size_t)(I0 + ti*8 + i)*DD + tj*4] = o4;
  }
}

// ---------------------------------------------------------------------------
// Head combine: out[b,s,v] = sum_h qkv[b,h,s,v] * w_o[h]
// ---------------------------------------------------------------------------
__global__ __launch_bounds__(256) void reduce_kernel(const float* __restrict__ w_o,
                                                     float* __restrict__ out) {
  int idx = blockIdx.x * 256 + threadIdx.x;
  if (idx >= BB*SS*DD) return;
  int b = idx / (SS*DD);
  int rem = idx - b * (SS*DD);
  float s = 0.f;
  #pragma unroll
  for (int h = 0; h < HH; h++)
    s += g_o[(size_t)(b*HH + h) * SS * DD + rem] * w_o[h];
  out[idx] = s;
}

extern "C" void kernel_launch(void* const* d_in, const int* in_sizes, int n_in,
                              void* d_out, int out_size) {
  const float* xs = (const float*)d_in[0];
  const float* wq = (const float*)d_in[1];
  const float* wk = (const float*)d_in[2];
  const float* wv = (const float*)d_in[3];
  const float* wo = (const float*)d_in[4];
  const float* ak = (const float*)d_in[5];

  proj_kernel<<<dim3(SS/64, BB*HH, 3), 256>>>(xs, wq, wk, wv);

  cudaFuncSetAttribute(attn_kernel, cudaFuncAttributeMaxDynamicSharedMemorySize,
                       SMEM_FLOATS * 4);
  attn_kernel<<<dim3(SS/TI, BB*HH), 256, SMEM_FLOATS * 4>>>(ak);

  reduce_kernel<<<(BB*SS*DD + 255) / 256, 256>>>(wo, (float*)d_out);
}